// round 16
// baseline (speedup 1.0000x reference)
#include <cuda_runtime.h>
#include <math.h>
#include <cstdint>
#include <mma.h>

using namespace nvcuda;

// Problem constants
#define BB 16
#define QQ 300
#define CC 256
#define NHH 8
#define DHH 32
#define SUMP 16
#define SS 8500
#define BQ (BB*QQ)        // 4800

#define KTOT 256          // GEMM K
#define NKS 32            // k-steps of 8

#define AS 260            // sA row stride (floats)
#define BS 392            // sB row stride (floats)
#define DS2 392           // sD row stride (floats)

// smem layout (floats): sA [32][260] = 8320 ; sB [2][8][392] = 6272 ; total 14592
// epilogue: sD [32][392] = 12544 overlaps the whole region after mainloop.
#define SA_OFF 0
#define SB_OFF (32 * AS)                 // 8320
#define SM_FLOATS (SB_OFF + 2 * 8 * BS)  // 14592
#define SMEM_K1_BYTES (SM_FLOATS * 4)    // 58368

// scratch
__device__ float g_loc[BQ * 256];

__device__ __constant__ int cWl[4]    = {80, 40, 20, 10};
__device__ __constant__ int cStart[4] = {0, 6400, 8000, 8400};

__device__ __forceinline__ float tf32r(float x) {
    uint32_t u;
    asm("cvt.rna.tf32.f32 %0, %1;" : "=r"(u) : "f"(x));
    return __uint_as_float(u);
}

typedef wmma::fragment<wmma::matrix_a, 16, 16, 8, wmma::precision::tf32, wmma::row_major> FragA;
typedef wmma::fragment<wmma::matrix_b, 16, 16, 8, wmma::precision::tf32, wmma::row_major> FragB;
typedef wmma::fragment<wmma::accumulator, 16, 16, 8, float> FragC;

// stage one k-step (8 k-rows x 384 n-cols) of [offk|attnk] into sB buffer,
// coalesced float4 from the k-major weight matrices. 768 float4 slots,
// 3 per thread.
__device__ __forceinline__ void stage_b(float* sB, const float* __restrict__ offk,
                                        const float* __restrict__ attnk,
                                        int ks, int tid)
{
#pragma unroll
    for (int i = 0; i < 3; i++) {
        const int s  = tid * 3 + i;        // 0..767
        const int kr = s / 96;             // local k-row 0..7
        const int c4 = s % 96;             // float4 col 0..95
        const int k  = ks * 8 + kr;
        float4 v = (c4 < 64) ? ((const float4*)offk)[(size_t)k * 64 + c4]
                             : ((const float4*)attnk)[(size_t)k * 32 + (c4 - 64)];
        *(float4*)&sB[kr * BS + c4 * 4] = v;
    }
}

// ---------------------------------------------------------------------------
// K1: self-contained tf32 WMMA GEMM — NO prep kernel.
// A: per-CTA 32x256 hs slab staged coalesced into smem.
// B: streamed per-k-step from gmem (coalesced float4, k-major rows are
//    contiguous) into double-buffered smem; fragments loaded via LDS.
// tf32 rounding applied in registers to both operands. Fused loc/softmax
// epilogue. Block = 256 (8 warps = 8 n-slices of 48); warp = 2qt x 3nt.
// Grid = 150 (32 q per CTA) -> 2 CTAs/SM.
// ---------------------------------------------------------------------------
__global__ __launch_bounds__(256, 2) void dfine_k1(
    const float* __restrict__ hs,      // (BQ,256)
    const float* __restrict__ offk,    // (256,256) k-major
    const float* __restrict__ attnk,   // (256,128) k-major
    const float* __restrict__ refp,    // (BQ,4)
    const float* __restrict__ offb,    // (256,)
    const float* __restrict__ attnb,   // (128,)
    const float* __restrict__ nps,     // (16,)
    float* __restrict__ attn_out)      // (BQ,128)
{
    extern __shared__ float sm[];
    float* sA = sm + SA_OFF;           // [32][260]
    float* sB = sm + SB_OFF;           // [2][8][392]
    float* sD = sm;                    // [32][392] after mainloop
    __shared__ float sRef[32 * 4];

    const int tid  = threadIdx.x;
    const int warp = tid >> 5;
    const int ns   = warp;             // n-slice (0..7), 48 cols each
    const int m0   = blockIdx.x * 32;

    if (tid < 32) ((float4*)sRef)[tid] = ((const float4*)refp)[m0 + tid];

    // stage A: this CTA's 32x256 hs slab, coalesced float4
    {
        const float4* src = (const float4*)(hs + (size_t)m0 * KTOT);
#pragma unroll
        for (int i = 0; i < 8; i++) {
            const int s = tid + i * 256;
            const int r = s >> 6, c4 = s & 63;
            *(float4*)&sA[r * AS + c4 * 4] = src[s];
        }
    }
    // stage B k-step 0 into buffer 0
    stage_b(sB, offk, attnk, 0, tid);
    __syncthreads();

    FragC acc[2][3];
#pragma unroll
    for (int i = 0; i < 2; i++)
#pragma unroll
        for (int j = 0; j < 3; j++) wmma::fill_fragment(acc[i][j], 0.f);

    for (int ks = 0; ks < NKS; ks++) {
        float* sBc = sB + (ks & 1) * 8 * BS;          // compute buffer
        // prefetch next k-step into the other buffer
        if (ks < NKS - 1)
            stage_b(sB + ((ks + 1) & 1) * 8 * BS, offk, attnk, ks + 1, tid);

        FragA a[2];
#pragma unroll
        for (int i = 0; i < 2; i++) {
            wmma::load_matrix_sync(a[i], sA + (i * 16) * AS + ks * 8, AS);
#pragma unroll
            for (int e = 0; e < 4; e++) a[i].x[e] = tf32r(a[i].x[e]);
        }
#pragma unroll
        for (int j = 0; j < 3; j++) {
            FragB b;
            wmma::load_matrix_sync(b, sBc + ns * 48 + j * 16, BS);
#pragma unroll
            for (int e = 0; e < 4; e++) b.x[e] = tf32r(b.x[e]);
#pragma unroll
            for (int i = 0; i < 2; i++)
                wmma::mma_sync(acc[i][j], a[i], b, acc[i][j]);
        }
        __syncthreads();   // staging(ks+1) done AND compute(ks) done
    }

    // store D [32 rows][384 cols] to smem (overlaps sA/sB, both dead)
#pragma unroll
    for (int i = 0; i < 2; i++)
#pragma unroll
        for (int j = 0; j < 3; j++)
            wmma::store_matrix_sync(sD + (size_t)i * 16 * DS2 + ns * 48 + j * 16,
                                    acc[i][j], DS2, wmma::mem_row_major);
    __syncthreads();

    // ---- offset epilogue: thread = offset col (0..255), 32 rows ----
    {
        const int j = tid;
        const int axis = j & 1, p = (j >> 1) & 15;
        const float bias  = __ldg(offb + j);
        const float scale = __ldg(nps + p) * 0.5f;
#pragma unroll 4
        for (int r = 0; r < 32; r++) {
            float o   = sD[r * DS2 + j];
            float ctr = sRef[r * 4 + axis];
            float wh  = sRef[r * 4 + 2 + axis];
            g_loc[(size_t)(m0 + r) * 256 + j] = fmaf((o + bias) * scale, wh, ctr);
        }
    }

    // ---- attn epilogue: warp = head, lane = row ----
    {
        const int h = warp, r = tid & 31;
        float lg[16];
        float mx = -1e30f;
#pragma unroll
        for (int p = 0; p < 16; p++) {
            lg[p] = sD[r * DS2 + 256 + h * 16 + p] + __ldg(attnb + h * 16 + p);
            mx = fmaxf(mx, lg[p]);
        }
        float s = 0.f;
#pragma unroll
        for (int p = 0; p < 16; p++) { lg[p] = __expf(lg[p] - mx); s += lg[p]; }
        const float inv = 1.f / s;
        float4* dst = (float4*)(attn_out + (size_t)(m0 + r) * 128 + h * 16);
#pragma unroll
        for (int q4 = 0; q4 < 4; q4++)
            dst[q4] = make_float4(lg[q4*4] * inv, lg[q4*4+1] * inv,
                                  lg[q4*4+2] * inv, lg[q4*4+3] * inv);
    }
}

// ---------------------------------------------------------------------------
// K2: per-query gather + weighted accumulate (at the LTS throughput floor:
// 314 MB of gather lines / ~11 TB/s = 28.6 us).
// ---------------------------------------------------------------------------
__global__ __launch_bounds__(256) void dfine_k2(
    const float* __restrict__ enc,
    const float* __restrict__ attn,
    float* __restrict__ out)
{
    __shared__ int4   sI[128];
    __shared__ float4 sWt[128];

    const int bq = blockIdx.x;
    const int t  = threadIdx.x;
    const int b  = bq / QQ;

    if (t < 128) {
        const int h   = t >> 4;
        const int p   = t & 15;
        const int lvl = p >> 2;
        const int Wl    = cWl[lvl];
        const int start = cStart[lvl];
        const float Wf  = (float)Wl;

        float lx = g_loc[(size_t)bq * 256 + h * 32 + p * 2];
        float ly = g_loc[(size_t)bq * 256 + h * 32 + p * 2 + 1];
        float aw = attn[(size_t)bq * 128 + t];

        float x = lx * Wf - 0.5f;
        float y = ly * Wf - 0.5f;
        float x0f = floorf(x), y0f = floorf(y);
        float fx = x - x0f, fy = y - y0f;
        int x0 = (int)x0f, y0 = (int)y0f;
        int x1 = x0 + 1,   y1 = y0 + 1;

        bool xv0 = ((unsigned)x0 < (unsigned)Wl);
        bool xv1 = ((unsigned)x1 < (unsigned)Wl);
        bool yv0 = ((unsigned)y0 < (unsigned)Wl);
        bool yv1 = ((unsigned)y1 < (unsigned)Wl);

        float w00 = (1.f - fx) * (1.f - fy) * aw;
        float w10 = fx * (1.f - fy) * aw;
        float w01 = (1.f - fx) * fy * aw;
        float w11 = fx * fy * aw;

        int4 I; float4 Wv;
        I.x = (xv0 & yv0) ? start + y0 * Wl + x0 : start;
        I.y = (xv1 & yv0) ? start + y0 * Wl + x1 : start;
        I.z = (xv0 & yv1) ? start + y1 * Wl + x0 : start;
        I.w = (xv1 & yv1) ? start + y1 * Wl + x1 : start;
        Wv.x = (xv0 & yv0) ? w00 : 0.f;
        Wv.y = (xv1 & yv0) ? w10 : 0.f;
        Wv.z = (xv0 & yv1) ? w01 : 0.f;
        Wv.w = (xv1 & yv1) ? w11 : 0.f;

        sI[t]  = I;
        sWt[t] = Wv;
    }
    __syncthreads();

    const int h    = t >> 5;
    const int lane = t & 31;
    const float* vbase = enc + (size_t)b * SS * CC + h * DHH + lane;

    float acc = 0.f;
#pragma unroll
    for (int p = 0; p < SUMP; p++) {
        int4   I  = sI[h * 16 + p];
        float4 Wv = sWt[h * 16 + p];
        acc = fmaf(Wv.x, __ldg(vbase + (size_t)I.x * CC), acc);
        acc = fmaf(Wv.y, __ldg(vbase + (size_t)I.y * CC), acc);
        acc = fmaf(Wv.z, __ldg(vbase + (size_t)I.z * CC), acc);
        acc = fmaf(Wv.w, __ldg(vbase + (size_t)I.w * CC), acc);
    }

    out[(size_t)bq * CC + h * DHH + lane] = acc;
}

// ---------------------------------------------------------------------------
// Launch: two kernels only (no prep).
// ---------------------------------------------------------------------------
extern "C" void kernel_launch(void* const* d_in, const int* in_sizes, int n_in,
                              void* d_out, int out_size) {
    const float* hs    = (const float*)d_in[0];
    const float* enc   = (const float*)d_in[1];
    const float* refp  = (const float*)d_in[2];
    const float* offk  = (const float*)d_in[3];
    const float* offb  = (const float*)d_in[4];
    const float* attnk = (const float*)d_in[5];
    const float* attnb = (const float*)d_in[6];
    const float* nps   = (const float*)d_in[7];

    float* out      = (float*)d_out;
    float* attn_out = out + (size_t)BQ * CC;

    cudaFuncSetAttribute(dfine_k1, cudaFuncAttributeMaxDynamicSharedMemorySize,
                         SMEM_K1_BYTES);

    dfine_k1<<<150, 256, SMEM_K1_BYTES>>>(hs, offk, attnk, refp, offb,
                                          attnb, nps, attn_out);
    dfine_k2<<<BQ, 256>>>(enc, attn_out, out);
}

// round 17
// speedup vs baseline: 1.2088x; 1.2088x over previous
#include <cuda_runtime.h>
#include <math.h>
#include <cstdint>
#include <mma.h>

using namespace nvcuda;

// Problem constants
#define BB 16
#define QQ 300
#define CC 256
#define NHH 8
#define DHH 32
#define SUMP 16
#define SS 8500
#define BQ (BB*QQ)        // 4800

#define KTOT 256          // GEMM K
#define NKS 32            // k-steps of 8

#define AS 260            // sA row stride (floats): a-frag LDS conflict-free
#define BS 392            // sB row stride (floats): b-frag LDS conflict-free
#define DS2 392           // sD row stride (floats)

// smem (floats): sA [32][260]=8320 ; sB ring 4x[8][392]=12544 ; total 20864
// epilogue: sD [32][392]=12544 overlaps the region after the mainloop.
#define SA_OFF 0
#define SB_OFF (32 * AS)                  // 8320
#define SM_FLOATS (SB_OFF + 4 * 8 * BS)   // 20864
#define SMEM_K1_BYTES (SM_FLOATS * 4)     // 83456  -> 2 CTAs/SM (167KB<=228KB)

// scratch
__device__ float g_loc[BQ * 256];

__device__ __constant__ int cWl[4]    = {80, 40, 20, 10};
__device__ __constant__ int cStart[4] = {0, 6400, 8000, 8400};

__device__ __forceinline__ float tf32r(float x) {
    uint32_t u;
    asm("cvt.rna.tf32.f32 %0, %1;" : "=r"(u) : "f"(x));
    return __uint_as_float(u);
}
__device__ __forceinline__ uint32_t smem_u32(const void* p) {
    uint32_t a;
    asm("{ .reg .u64 t; cvta.to.shared.u64 t, %1; cvt.u32.u64 %0, t; }" : "=r"(a) : "l"(p));
    return a;
}
__device__ __forceinline__ void cp16(uint32_t dst, const void* src) {
    asm volatile("cp.async.cg.shared.global [%0], [%1], 16;" :: "r"(dst), "l"(src) : "memory");
}
#define CP_COMMIT() asm volatile("cp.async.commit_group;" ::: "memory")

typedef wmma::fragment<wmma::matrix_a, 16, 16, 8, wmma::precision::tf32, wmma::row_major> FragA;
typedef wmma::fragment<wmma::matrix_b, 16, 16, 8, wmma::precision::tf32, wmma::row_major> FragB;
typedef wmma::fragment<wmma::accumulator, 16, 16, 8, float> FragC;

// async-stage one k-step (8 k-rows x 384 cols) of [offk|attnk] into an sB buf.
// 768 float4 slots; thread t handles s = t, t+256, t+512 (coalesced).
__device__ __forceinline__ void stage_b_async(float* sBuf,
                                              const float* __restrict__ offk,
                                              const float* __restrict__ attnk,
                                              int ks, int tid)
{
#pragma unroll
    for (int i = 0; i < 3; i++) {
        const int s  = tid + i * 256;      // 0..767
        const int kr = s / 96;             // local k-row 0..7
        const int c4 = s % 96;             // float4 col 0..95
        const int k  = ks * 8 + kr;
        const float* src = (c4 < 64) ? (const float*)((const float4*)offk + (size_t)k * 64 + c4)
                                     : (const float*)((const float4*)attnk + (size_t)k * 32 + (c4 - 64));
        cp16(smem_u32(&sBuf[kr * BS + c4 * 4]), src);
    }
}

// ---------------------------------------------------------------------------
// K1: self-contained tf32 WMMA GEMM, cp.async 4-deep B pipeline — no prep
// kernel, no inter-CTA gate. A: per-CTA 32x256 hs slab (cp.async, group 0).
// B: k-step ring staged 3 steps ahead; fragments via conflict-free LDS.
// tf32 rounding in registers (same numerics as rounds 9-16).
// Block = 256 (8 warps = 8 n-slices of 48); warp = 2qt x 3nt.
// Grid = 150 (32 q per CTA) -> 2 CTAs/SM, one wave.
// ---------------------------------------------------------------------------
__global__ __launch_bounds__(256, 2) void dfine_k1(
    const float* __restrict__ hs,      // (BQ,256)
    const float* __restrict__ offk,    // (256,256) k-major
    const float* __restrict__ attnk,   // (256,128) k-major
    const float* __restrict__ refp,    // (BQ,4)
    const float* __restrict__ offb,    // (256,)
    const float* __restrict__ attnb,   // (128,)
    const float* __restrict__ nps,     // (16,)
    float* __restrict__ attn_out)      // (BQ,128)
{
    extern __shared__ float sm[];
    float* sA = sm + SA_OFF;           // [32][260]
    float* sB = sm + SB_OFF;           // ring: 4 x [8][392]
    float* sD = sm;                    // [32][392] after mainloop
    __shared__ float sRef[32 * 4];

    const int tid  = threadIdx.x;
    const int warp = tid >> 5;
    const int ns   = warp;             // n-slice (0..7), 48 cols each
    const int m0   = blockIdx.x * 32;

    if (tid < 32) ((float4*)sRef)[tid] = ((const float4*)refp)[m0 + tid];

    // group 0: A slab + B k-step 0
    {
        const float4* src = (const float4*)(hs + (size_t)m0 * KTOT);
#pragma unroll
        for (int i = 0; i < 8; i++) {
            const int s = tid + i * 256;
            const int r = s >> 6, c4 = s & 63;
            cp16(smem_u32(&sA[r * AS + c4 * 4]), src + s);
        }
        stage_b_async(sB, offk, attnk, 0, tid);
        CP_COMMIT();
    }
    // groups 1,2: B k-steps 1,2
    stage_b_async(sB + 1 * 8 * BS, offk, attnk, 1, tid); CP_COMMIT();
    stage_b_async(sB + 2 * 8 * BS, offk, attnk, 2, tid); CP_COMMIT();

    FragC acc[2][3];
#pragma unroll
    for (int i = 0; i < 2; i++)
#pragma unroll
        for (int j = 0; j < 3; j++) wmma::fill_fragment(acc[i][j], 0.f);

    // mainloop: group N == k-step N data (empty commits keep the count)
    for (int ks = 0; ks < NKS; ks++) {
        asm volatile("cp.async.wait_group 2;" ::: "memory");  // groups <= ks done
        __syncthreads();

        float* sBc = sB + (ks & 3) * 8 * BS;
        FragA a[2];
#pragma unroll
        for (int i = 0; i < 2; i++) {
            wmma::load_matrix_sync(a[i], sA + (i * 16) * AS + ks * 8, AS);
#pragma unroll
            for (int e = 0; e < 4; e++) a[i].x[e] = tf32r(a[i].x[e]);
        }
#pragma unroll
        for (int j = 0; j < 3; j++) {
            FragB b;
            wmma::load_matrix_sync(b, sBc + ns * 48 + j * 16, BS);
#pragma unroll
            for (int e = 0; e < 4; e++) b.x[e] = tf32r(b.x[e]);
#pragma unroll
            for (int i = 0; i < 2; i++)
                wmma::mma_sync(acc[i][j], a[i], b, acc[i][j]);
        }

        // stage k-step ks+3 into the buffer just freed NEXT round; the
        // buffer (ks+3)&3 == (ks-1)&3 was consumed at iteration ks-1, and
        // all warps passed this iteration's barrier before we overwrite it.
        __syncthreads();
        if (ks + 3 < NKS)
            stage_b_async(sB + ((ks + 3) & 3) * 8 * BS, offk, attnk, ks + 3, tid);
        CP_COMMIT();    // possibly empty — keeps group<->k-step alignment
    }
    __syncthreads();   // sA/sB dead; safe to overwrite with sD

    // store D [32 rows][384 cols] to smem
#pragma unroll
    for (int i = 0; i < 2; i++)
#pragma unroll
        for (int j = 0; j < 3; j++)
            wmma::store_matrix_sync(sD + (size_t)i * 16 * DS2 + ns * 48 + j * 16,
                                    acc[i][j], DS2, wmma::mem_row_major);
    __syncthreads();

    // ---- offset epilogue: thread = offset col (0..255), 32 rows ----
    {
        const int j = tid;
        const int axis = j & 1, p = (j >> 1) & 15;
        const float bias  = __ldg(offb + j);
        const float scale = __ldg(nps + p) * 0.5f;
#pragma unroll 4
        for (int r = 0; r < 32; r++) {
            float o   = sD[r * DS2 + j];
            float ctr = sRef[r * 4 + axis];
            float wh  = sRef[r * 4 + 2 + axis];
            g_loc[(size_t)(m0 + r) * 256 + j] = fmaf((o + bias) * scale, wh, ctr);
        }
    }

    // ---- attn epilogue: warp = head, lane = row ----
    {
        const int h = warp, r = tid & 31;
        float lg[16];
        float mx = -1e30f;
#pragma unroll
        for (int p = 0; p < 16; p++) {
            lg[p] = sD[r * DS2 + 256 + h * 16 + p] + __ldg(attnb + h * 16 + p);
            mx = fmaxf(mx, lg[p]);
        }
        float s = 0.f;
#pragma unroll
        for (int p = 0; p < 16; p++) { lg[p] = __expf(lg[p] - mx); s += lg[p]; }
        const float inv = 1.f / s;
        float4* dst = (float4*)(attn_out + (size_t)(m0 + r) * 128 + h * 16);
#pragma unroll
        for (int q4 = 0; q4 < 4; q4++)
            dst[q4] = make_float4(lg[q4*4] * inv, lg[q4*4+1] * inv,
                                  lg[q4*4+2] * inv, lg[q4*4+3] * inv);
    }
}

// ---------------------------------------------------------------------------
// K2: per-query gather + weighted accumulate (at the LTS throughput floor:
// 314 MB of gather lines / ~11 TB/s = 28.6 us).
// ---------------------------------------------------------------------------
__global__ __launch_bounds__(256) void dfine_k2(
    const float* __restrict__ enc,
    const float* __restrict__ attn,
    float* __restrict__ out)
{
    __shared__ int4   sI[128];
    __shared__ float4 sWt[128];

    const int bq = blockIdx.x;
    const int t  = threadIdx.x;
    const int b  = bq / QQ;

    if (t < 128) {
        const int h   = t >> 4;
        const int p   = t & 15;
        const int lvl = p >> 2;
        const int Wl    = cWl[lvl];
        const int start = cStart[lvl];
        const float Wf  = (float)Wl;

        float lx = g_loc[(size_t)bq * 256 + h * 32 + p * 2];
        float ly = g_loc[(size_t)bq * 256 + h * 32 + p * 2 + 1];
        float aw = attn[(size_t)bq * 128 + t];

        float x = lx * Wf - 0.5f;
        float y = ly * Wf - 0.5f;
        float x0f = floorf(x), y0f = floorf(y);
        float fx = x - x0f, fy = y - y0f;
        int x0 = (int)x0f, y0 = (int)y0f;
        int x1 = x0 + 1,   y1 = y0 + 1;

        bool xv0 = ((unsigned)x0 < (unsigned)Wl);
        bool xv1 = ((unsigned)x1 < (unsigned)Wl);
        bool yv0 = ((unsigned)y0 < (unsigned)Wl);
        bool yv1 = ((unsigned)y1 < (unsigned)Wl);

        float w00 = (1.f - fx) * (1.f - fy) * aw;
        float w10 = fx * (1.f - fy) * aw;
        float w01 = (1.f - fx) * fy * aw;
        float w11 = fx * fy * aw;

        int4 I; float4 Wv;
        I.x = (xv0 & yv0) ? start + y0 * Wl + x0 : start;
        I.y = (xv1 & yv0) ? start + y0 * Wl + x1 : start;
        I.z = (xv0 & yv1) ? start + y1 * Wl + x0 : start;
        I.w = (xv1 & yv1) ? start + y1 * Wl + x1 : start;
        Wv.x = (xv0 & yv0) ? w00 : 0.f;
        Wv.y = (xv1 & yv0) ? w10 : 0.f;
        Wv.z = (xv0 & yv1) ? w01 : 0.f;
        Wv.w = (xv1 & yv1) ? w11 : 0.f;

        sI[t]  = I;
        sWt[t] = Wv;
    }
    __syncthreads();

    const int h    = t >> 5;
    const int lane = t & 31;
    const float* vbase = enc + (size_t)b * SS * CC + h * DHH + lane;

    float acc = 0.f;
#pragma unroll
    for (int p = 0; p < SUMP; p++) {
        int4   I  = sI[h * 16 + p];
        float4 Wv = sWt[h * 16 + p];
        acc = fmaf(Wv.x, __ldg(vbase + (size_t)I.x * CC), acc);
        acc = fmaf(Wv.y, __ldg(vbase + (size_t)I.y * CC), acc);
        acc = fmaf(Wv.z, __ldg(vbase + (size_t)I.z * CC), acc);
        acc = fmaf(Wv.w, __ldg(vbase + (size_t)I.w * CC), acc);
    }

    out[(size_t)bq * CC + h * DHH + lane] = acc;
}

// ---------------------------------------------------------------------------
// Launch: two kernels only (no prep).
// ---------------------------------------------------------------------------
extern "C" void kernel_launch(void* const* d_in, const int* in_sizes, int n_in,
                              void* d_out, int out_size) {
    const float* hs    = (const float*)d_in[0];
    const float* enc   = (const float*)d_in[1];
    const float* refp  = (const float*)d_in[2];
    const float* offk  = (const float*)d_in[3];
    const float* offb  = (const float*)d_in[4];
    const float* attnk = (const float*)d_in[5];
    const float* attnb = (const float*)d_in[6];
    const float* nps   = (const float*)d_in[7];

    float* out      = (float*)d_out;
    float* attn_out = out + (size_t)BQ * CC;

    cudaFuncSetAttribute(dfine_k1, cudaFuncAttributeMaxDynamicSharedMemorySize,
                         SMEM_K1_BYTES);

    dfine_k1<<<150, 256, SMEM_K1_BYTES>>>(hs, offk, attnk, refp, offb,
                                          attnb, nps, attn_out);
    dfine_k2<<<BQ, 256>>>(enc, attn_out, out);
}